// round 15
// baseline (speedup 1.0000x reference)
#include <cuda_runtime.h>
#include <cuda_bf16.h>
#include <cuda_fp16.h>
#include <cstdint>

#define NROWS 16384
#define HID   2048
#define LAT   16384
#define TOPK  32
#define NCAND 48

// ---------------------------------------------------------------------------
// Device scratch (allocation-free)
// ---------------------------------------------------------------------------
__device__ __nv_bfloat16 g_xb[(size_t)NROWS * HID];   // bf16(x - b1)
__device__ __nv_bfloat16 g_wb[(size_t)LAT * HID];     // bf16(enc_w)
__device__ __half g_dec_h[(size_t)LAT * HID];         // fp16 dec_w transposed
__device__ float g_top_val[(size_t)NROWS * TOPK];
__device__ int   g_top_idx[(size_t)NROWS * TOPK];
__device__ int   g_cand_idx[(size_t)NROWS * NCAND];

// ---------------------------------------------------------------------------
// Helpers
// ---------------------------------------------------------------------------
__device__ __forceinline__ uint32_t smem_u32(const void* p) {
    uint32_t a;
    asm("{ .reg .u64 t; cvta.to.shared.u64 t, %1; cvt.u32.u64 %0, t; }" : "=r"(a) : "l"(p));
    return a;
}
#define CP16(dst, src) \
    asm volatile("cp.async.cg.shared.global [%0], [%1], 16;" :: "r"(dst), "l"(src))
#define CP_COMMIT() asm volatile("cp.async.commit_group;" ::: "memory")
#define CP_WAIT1()  asm volatile("cp.async.wait_group 1;" ::: "memory")

#define LDSM4(r0, r1, r2, r3, addr) \
    asm volatile("ldmatrix.sync.aligned.m8n8.x4.shared.b16 {%0,%1,%2,%3}, [%4];" \
                 : "=r"(r0), "=r"(r1), "=r"(r2), "=r"(r3) : "r"(addr))
#define MMA16816(c, a, b) \
    asm volatile("mma.sync.aligned.m16n8k16.row.col.f32.bf16.bf16.f32 " \
                 "{%0,%1,%2,%3}, {%4,%5,%6,%7}, {%8,%9}, {%0,%1,%2,%3};" \
                 : "+f"((c)[0]), "+f"((c)[1]), "+f"((c)[2]), "+f"((c)[3]) \
                 : "r"((a)[0]), "r"((a)[1]), "r"((a)[2]), "r"((a)[3]), \
                   "r"((b)[0]), "r"((b)[1]))

// ---------------------------------------------------------------------------
// HMMA GEMM (R12/R13 proven): 128x128x64 tiles, 3-stage cp.async, 8 warps,
// 2 CTAs/SM, LDSM4 for both A and B (ni-pairs), multistage prefetch order.
// smem row stride 144B: (144*r) mod 128 = 16*r -> conflict-free ldmatrix.
// ---------------------------------------------------------------------------
#define BM 128
#define BN 128
#define BK 64
#define ROWB 144
#define STG_BYTES (2 * BM * ROWB)        // A + B per stage = 36864 B
#define GEMM_SMEM (3 * STG_BYTES)        // 110592 B
#define NIT (HID / BK)                   // 32

__device__ __forceinline__ void load_stage_g(uint32_t sb, int s, int k0,
                                             int rowBase, int colBase, int tid)
{
    const uint32_t a0 = sb + s * STG_BYTES;
    const uint32_t b0 = a0 + BM * ROWB;
    const __nv_bfloat16* ag = g_xb + (size_t)rowBase * HID + k0;
    const __nv_bfloat16* bg = g_wb + (size_t)colBase * HID + k0;
#pragma unroll
    for (int i = 0; i < 4; ++i) {               // A: 1024 x 16B lines
        int c = tid + i * 256;
        int r = c >> 3, seg = c & 7;
        CP16(a0 + r * ROWB + seg * 16, ag + (size_t)r * HID + seg * 8);
    }
#pragma unroll
    for (int i = 0; i < 4; ++i) {               // B: 1024 x 16B lines
        int c = tid + i * 256;
        int r = c >> 3, seg = c & 7;
        CP16(b0 + r * ROWB + seg * 16, bg + (size_t)r * HID + seg * 8);
    }
}

#define LOAD_FRAGS_AT(slot, ab, bb, ks)                                       \
    do {                                                                      \
        _Pragma("unroll")                                                     \
        for (int mi = 0; mi < 4; ++mi)                                        \
            LDSM4(af[slot][mi][0], af[slot][mi][1],                           \
                  af[slot][mi][2], af[slot][mi][3],                           \
                  (ab) + (uint32_t)(mi * 16) * ROWB + (ks) * 32);             \
        _Pragma("unroll")                                                     \
        for (int ni = 0; ni < 4; ni += 2)                                     \
            LDSM4(bf[slot][ni][0], bf[slot][ni][1],                           \
                  bf[slot][ni + 1][0], bf[slot][ni + 1][1],                   \
                  (bb) + (uint32_t)(ni * 8) * ROWB + (ks) * 32);              \
    } while (0)

__global__ void __launch_bounds__(256, 2)
gemm_hmma(const float* __restrict__ encb, __nv_bfloat16* __restrict__ approx)
{
    extern __shared__ char smem[];
    const uint32_t sb = smem_u32(smem);
    const int tid = threadIdx.x, wid = tid >> 5, lane = tid & 31;
    const int wm = wid >> 2, wn = wid & 3;      // 2x4 warp grid
    const int rowBase = blockIdx.y * BM;
    const int colBase = blockIdx.x * BN;

    float acc[4][4][4];
#pragma unroll
    for (int mi = 0; mi < 4; ++mi)
#pragma unroll
        for (int ni = 0; ni < 4; ++ni)
#pragma unroll
            for (int q = 0; q < 4; ++q) acc[mi][ni][q] = 0.f;

    load_stage_g(sb, 0, 0 * BK, rowBase, colBase, tid); CP_COMMIT();
    load_stage_g(sb, 1, 1 * BK, rowBase, colBase, tid); CP_COMMIT();

    const uint32_t a_row_off = (uint32_t)(wm * 64 + (lane & 15)) * ROWB + (lane >> 4) * 16;
    const uint32_t b_row_off =
        (uint32_t)(wn * 32 + ((lane >> 4) & 1) * 8 + (lane & 7)) * ROWB +
        ((lane >> 3) & 1) * 16;

    uint32_t af[2][4][4], bf[2][4][2];

    CP_WAIT1();
    __syncthreads();
    LOAD_FRAGS_AT(0, sb + a_row_off, sb + BM * ROWB + b_row_off, 0);

    int buf = 0;
    for (int it = 0; it < NIT; ++it) {
        if (it + 2 < NIT)
            load_stage_g(sb, (it + 2) % 3, (it + 2) * BK, rowBase, colBase, tid);
        CP_COMMIT();

        const uint32_t ab  = sb + buf * STG_BYTES + a_row_off;
        const uint32_t bb  = sb + buf * STG_BYTES + BM * ROWB + b_row_off;
        const int nbuf = (buf == 2) ? 0 : buf + 1;
        const uint32_t abn = sb + nbuf * STG_BYTES + a_row_off;
        const uint32_t bbn = sb + nbuf * STG_BYTES + BM * ROWB + b_row_off;

#pragma unroll
        for (int ks = 0; ks < 4; ++ks) {
            const int cur = ks & 1, nx = cur ^ 1;
            if (ks < 3) {
                LOAD_FRAGS_AT(nx, ab, bb, ks + 1);
            } else {
                CP_WAIT1();
                __syncthreads();
                if (it + 1 < NIT)
                    LOAD_FRAGS_AT(nx, abn, bbn, 0);
            }
#pragma unroll
            for (int mi = 0; mi < 4; ++mi)
#pragma unroll
                for (int ni = 0; ni < 4; ++ni)
                    MMA16816(acc[mi][ni], af[cur][mi], bf[cur][ni]);
        }
        buf = nbuf;
    }

    // Epilogue: + enc_b, relu, direct bf16 store
    const int g  = lane >> 2;
    const int tg = lane & 3;
    float2 bias[4];
#pragma unroll
    for (int ni = 0; ni < 4; ++ni)
        bias[ni] = *(const float2*)(encb + colBase + wn * 32 + ni * 8 + tg * 2);

#pragma unroll
    for (int mi = 0; mi < 4; ++mi) {
        const size_t r0 = (size_t)(rowBase + wm * 64 + mi * 16 + g);
        const size_t r1 = r0 + 8;
#pragma unroll
        for (int ni = 0; ni < 4; ++ni) {
            const int col = colBase + wn * 32 + ni * 8 + tg * 2;
            float v00 = fmaxf(acc[mi][ni][0] + bias[ni].x, 0.f);
            float v01 = fmaxf(acc[mi][ni][1] + bias[ni].y, 0.f);
            float v10 = fmaxf(acc[mi][ni][2] + bias[ni].x, 0.f);
            float v11 = fmaxf(acc[mi][ni][3] + bias[ni].y, 0.f);
            __nv_bfloat162 p0 = __floats2bfloat162_rn(v00, v01);
            __nv_bfloat162 p1 = __floats2bfloat162_rn(v10, v11);
            *(__nv_bfloat162*)(approx + r0 * LAT + col) = p0;
            *(__nv_bfloat162*)(approx + r1 * LAT + col) = p1;
        }
    }
}

// ---------------------------------------------------------------------------
// Converters
// ---------------------------------------------------------------------------
__global__ void __launch_bounds__(256) conv_x(const float* __restrict__ x,
                                              const float* __restrict__ b1)
{
    size_t i = ((size_t)blockIdx.x * 256 + threadIdx.x) * 8;
    int col = (int)(i & (HID - 1));
    float4 a0 = *(const float4*)(x + i);
    float4 a1 = *(const float4*)(x + i + 4);
    float4 c0 = *(const float4*)(b1 + col);
    float4 c1 = *(const float4*)(b1 + col + 4);
    __nv_bfloat162 p0 = __floats2bfloat162_rn(a0.x - c0.x, a0.y - c0.y);
    __nv_bfloat162 p1 = __floats2bfloat162_rn(a0.z - c0.z, a0.w - c0.w);
    __nv_bfloat162 p2 = __floats2bfloat162_rn(a1.x - c1.x, a1.y - c1.y);
    __nv_bfloat162 p3 = __floats2bfloat162_rn(a1.z - c1.z, a1.w - c1.w);
    *(uint4*)(g_xb + i) = make_uint4(*(uint32_t*)&p0, *(uint32_t*)&p1,
                                     *(uint32_t*)&p2, *(uint32_t*)&p3);
}

__global__ void __launch_bounds__(256) conv_w(const float* __restrict__ w)
{
    size_t i = ((size_t)blockIdx.x * 256 + threadIdx.x) * 8;
    float4 a0 = *(const float4*)(w + i);
    float4 a1 = *(const float4*)(w + i + 4);
    __nv_bfloat162 p0 = __floats2bfloat162_rn(a0.x, a0.y);
    __nv_bfloat162 p1 = __floats2bfloat162_rn(a0.z, a0.w);
    __nv_bfloat162 p2 = __floats2bfloat162_rn(a1.x, a1.y);
    __nv_bfloat162 p3 = __floats2bfloat162_rn(a1.z, a1.w);
    *(uint4*)(g_wb + i) = make_uint4(*(uint32_t*)&p0, *(uint32_t*)&p1,
                                     *(uint32_t*)&p2, *(uint32_t*)&p3);
}

// ---------------------------------------------------------------------------
// Transpose dec_w [HID, LAT] -> g_dec_h [LAT, HID] (fp16)
// ---------------------------------------------------------------------------
__global__ void __launch_bounds__(256) transpose_dec(const float* __restrict__ dw)
{
    __shared__ float t[32][33];
    const int j0 = blockIdx.x * 32;
    const int h0 = blockIdx.y * 32;
    const int tx = threadIdx.x, ty = threadIdx.y;
#pragma unroll
    for (int dy = 0; dy < 32; dy += 8)
        t[ty + dy][tx] = dw[(size_t)(h0 + ty + dy) * LAT + j0 + tx];
    __syncthreads();
#pragma unroll
    for (int dy = 0; dy < 32; dy += 8)
        g_dec_h[(size_t)(j0 + ty + dy) * HID + h0 + tx] = __float2half(t[tx][ty + dy]);
}

// ---------------------------------------------------------------------------
// Candidate top-48 per row on bf16 approx scores (u16 order == value order).
// uint4 loads; 2-pass histogram with pass-1 threshold 3.0 (bf16 0x4040) to
// cut smem atomics ~4.7x; exact-binary-search fallback when <NCAND exceed 3.0.
// rv[m] (m = 4*j + w) holds bf16 pair at element index 8*(tid + j*256) + 2*w.
// ---------------------------------------------------------------------------
#define CAND_I0(m) (8 * (tid + ((m) >> 2) * 256) + 2 * ((m) & 3))
#define T_PASS1 0x4040u    // bf16(3.0)

__global__ void __launch_bounds__(256) cand_kernel(const unsigned short* __restrict__ approx)
{
    __shared__ unsigned hist[256];
    __shared__ unsigned s_cnt, s_hi, s_g, s_t;
    __shared__ int s_m, s_e;
    __shared__ int gt_idx[NCAND];
    __shared__ int eq_idx[96];

    const int row = blockIdx.x;
    const int tid = threadIdx.x;
    const uint4* src4 = (const uint4*)(approx + (size_t)row * LAT);

    unsigned rv[32];
#pragma unroll
    for (int j = 0; j < 8; ++j) {
        uint4 q = src4[tid + j * 256];
        rv[4 * j + 0] = q.x; rv[4 * j + 1] = q.y;
        rv[4 * j + 2] = q.z; rv[4 * j + 3] = q.w;
    }

    // pass 1: count values > 3.0 and histogram their hi byte (64 bins 0x40..0x7F)
    hist[tid] = 0;
    if (tid == 0) s_cnt = 0;
    __syncthreads();
    unsigned cnt = 0;
#pragma unroll
    for (int m = 0; m < 32; ++m) {
        unsigned v = rv[m];
        unsigned l16 = v & 0xFFFFu, h16 = v >> 16;
        if (l16 > T_PASS1) { atomicAdd(&hist[(l16 >> 8) - 0x40], 1u); ++cnt; }
        if (h16 > T_PASS1) { atomicAdd(&hist[(h16 >> 8) - 0x40], 1u); ++cnt; }
    }
    cnt = __reduce_add_sync(0xFFFFFFFFu, cnt);
    if ((tid & 31) == 0) atomicAdd(&s_cnt, cnt);
    __syncthreads();
    const unsigned total = s_cnt;

    unsigned T;
    if (total >= NCAND) {
        if (tid == 0) {
            unsigned cum = 0;
            for (int b = 63; b >= 0; --b) {
                if (cum + hist[b] >= NCAND) { s_hi = (unsigned)b; s_g = cum; break; }
                cum += hist[b];
            }
        }
        __syncthreads();
        const unsigned hstar = s_hi + 0x40;
        const unsigned G = s_g;
        hist[tid] = 0;
        __syncthreads();
#pragma unroll
        for (int m = 0; m < 32; ++m) {
            unsigned v = rv[m];
            unsigned l16 = v & 0xFFFFu, h16 = v >> 16;
            if ((l16 >> 8) == hstar && l16 > T_PASS1) atomicAdd(&hist[l16 & 0xFF], 1u);
            if ((h16 >> 8) == hstar && h16 > T_PASS1) atomicAdd(&hist[h16 & 0xFF], 1u);
        }
        __syncthreads();
        if (tid == 0) {
            unsigned cum = G;
            for (int b = 255; b >= 0; --b) {
                cum += hist[b];
                if (cum >= NCAND) { s_t = (hstar << 8) | (unsigned)b; break; }
            }
        }
        __syncthreads();
        T = s_t;
    } else {
        // fallback: exact binary search; threshold known <= 3.0
        unsigned lo = 0u, hi = T_PASS1 + 1u;
        while (lo < hi) {
            unsigned mid = (lo + hi) >> 1;
            if (tid == 0) s_cnt = 0;
            __syncthreads();
            unsigned c = 0;
#pragma unroll
            for (int m = 0; m < 32; ++m) {
                unsigned v = rv[m];
                c += ((v & 0xFFFFu) > mid);
                c += ((v >> 16) > mid);
            }
            c = __reduce_add_sync(0xFFFFFFFFu, c);
            if ((tid & 31) == 0) atomicAdd(&s_cnt, c);
            __syncthreads();
            unsigned tc = s_cnt;
            __syncthreads();
            if (tc >= NCAND) lo = mid + 1; else hi = mid;
        }
        T = lo;
    }

    if (tid == 0) { s_m = 0; s_e = 0; }
    __syncthreads();
#pragma unroll
    for (int m = 0; m < 32; ++m) {
        unsigned v = rv[m];
        int i0 = CAND_I0(m);
        unsigned l16 = v & 0xFFFFu, h16 = v >> 16;
        if (l16 > T)       { int p = atomicAdd(&s_m, 1); if (p < NCAND) gt_idx[p] = i0; }
        else if (l16 == T) { int p = atomicAdd(&s_e, 1); if (p < 96)    eq_idx[p] = i0; }
        if (h16 > T)       { int p = atomicAdd(&s_m, 1); if (p < NCAND) gt_idx[p] = i0 + 1; }
        else if (h16 == T) { int p = atomicAdd(&s_e, 1); if (p < 96)    eq_idx[p] = i0 + 1; }
    }
    __syncthreads();
    if (tid < NCAND) {
        int m = s_m;
        int v = (tid < m) ? gt_idx[tid] : eq_idx[tid - m];
        g_cand_idx[(size_t)row * NCAND + tid] = v;
    }
}

// ---------------------------------------------------------------------------
// Exact fp32 rescore of 48 candidates + exact top-32 (jax tie-break: low idx)
// ---------------------------------------------------------------------------
__global__ void __launch_bounds__(256) rescore_kernel(const float* __restrict__ x,
                                                      const float* __restrict__ b1,
                                                      const float* __restrict__ w)
{
    __shared__ float xs[HID];
    __shared__ float vals[NCAND];
    __shared__ int   cidx[NCAND];
    const int row = blockIdx.x, tid = threadIdx.x;
    const int wid = tid >> 5, lid = tid & 31;

    const float4* xr = (const float4*)(x + (size_t)row * HID);
    const float4* br = (const float4*)b1;
#pragma unroll
    for (int i = 0; i < 2; ++i) {
        int idx = tid + i * 256;
        float4 a = xr[idx], b = br[idx];
        ((float4*)xs)[idx] = make_float4(a.x - b.x, a.y - b.y, a.z - b.z, a.w - b.w);
    }
    if (tid < NCAND) cidx[tid] = g_cand_idx[(size_t)row * NCAND + tid];
    __syncthreads();

    for (int c = wid; c < NCAND; c += 8) {
        const float4* wr = (const float4*)(w + (size_t)cidx[c] * HID);
        float acc = 0.f;
#pragma unroll
        for (int j = 0; j < 16; ++j) {
            float4 wv = wr[lid + j * 32];
            float4 xv = ((const float4*)xs)[lid + j * 32];
            acc = fmaf(wv.x, xv.x, acc);
            acc = fmaf(wv.y, xv.y, acc);
            acc = fmaf(wv.z, xv.z, acc);
            acc = fmaf(wv.w, xv.w, acc);
        }
#pragma unroll
        for (int o = 16; o; o >>= 1) acc += __shfl_xor_sync(0xFFFFFFFFu, acc, o);
        if (lid == 0) vals[c] = fmaxf(acc, 0.f);
    }
    __syncthreads();

    // warp 0: 32 rounds of argmax over 48 (val desc, idx asc)
    if (wid == 0) {
        float v0 = vals[lid];
        int   i0 = cidx[lid];
        float v1 = (lid < NCAND - 32) ? vals[lid + 32] : -2.f;
        int   i1 = (lid < NCAND - 32) ? cidx[lid + 32] : 0x7FFFFFFF;
        size_t base = (size_t)row * TOPK;
        for (int p = 0; p < TOPK; ++p) {
            float mv; int mi;
            if (v0 > v1 || (v0 == v1 && i0 <= i1)) { mv = v0; mi = i0; }
            else                                    { mv = v1; mi = i1; }
            float bv = mv; int bi = mi;
#pragma unroll
            for (int o = 16; o; o >>= 1) {
                float ov = __shfl_xor_sync(0xFFFFFFFFu, bv, o);
                int   oi = __shfl_xor_sync(0xFFFFFFFFu, bi, o);
                if (ov > bv || (ov == bv && oi < bi)) { bv = ov; bi = oi; }
            }
            if (lid == 0) { g_top_val[base + p] = bv; g_top_idx[base + p] = bi; }
            if (i0 == bi) v0 = -1.f;
            if (i1 == bi) v1 = -1.f;
        }
    }
}

// ---------------------------------------------------------------------------
// Scatter + sparse decode (fp16 decoder weights, fp32 accumulate)
// ---------------------------------------------------------------------------
__global__ void scatter_kernel(float* __restrict__ z)
{
    int i = blockIdx.x * 256 + threadIdx.x;
    if (i < NROWS * TOPK) {
        int row = i >> 5;
        z[(size_t)row * LAT + g_top_idx[i]] = g_top_val[i];
    }
}

__global__ void __launch_bounds__(256) decode_kernel(const float* __restrict__ decb,
                                                     float* __restrict__ xhat)
{
    const int row = blockIdx.x;
    const int tid = threadIdx.x;
    const int c0  = tid * 8;                 // 8 columns per thread
    float a[8];
    float4 b0 = ((const float4*)decb)[tid * 2];
    float4 b1 = ((const float4*)decb)[tid * 2 + 1];
    a[0] = b0.x; a[1] = b0.y; a[2] = b0.z; a[3] = b0.w;
    a[4] = b1.x; a[5] = b1.y; a[6] = b1.z; a[7] = b1.w;

    const size_t base = (size_t)row * TOPK;
#pragma unroll 4
    for (int k = 0; k < TOPK; ++k) {
        const int   idx = g_top_idx[base + k];
        const float v   = g_top_val[base + k];
        uint4 dv = *(const uint4*)(g_dec_h + (size_t)idx * HID + c0);
        float2 f0 = __half22float2(*(__half2*)&dv.x);
        float2 f1 = __half22float2(*(__half2*)&dv.y);
        float2 f2 = __half22float2(*(__half2*)&dv.z);
        float2 f3 = __half22float2(*(__half2*)&dv.w);
        a[0] = fmaf(v, f0.x, a[0]); a[1] = fmaf(v, f0.y, a[1]);
        a[2] = fmaf(v, f1.x, a[2]); a[3] = fmaf(v, f1.y, a[3]);
        a[4] = fmaf(v, f2.x, a[4]); a[5] = fmaf(v, f2.y, a[5]);
        a[6] = fmaf(v, f3.x, a[6]); a[7] = fmaf(v, f3.y, a[7]);
    }
    float4* out = (float4*)(xhat + (size_t)row * HID + c0);
    out[0] = make_float4(a[0], a[1], a[2], a[3]);
    out[1] = make_float4(a[4], a[5], a[6], a[7]);
}

// ---------------------------------------------------------------------------
// kernel_launch.  Inputs: x, b1, enc_w, enc_b, dec_w, dec_b, topk
// Output: [x_hat (N*HID) | z (N*LAT)] fp32.  z region doubles as bf16 scratch.
// ---------------------------------------------------------------------------
extern "C" void kernel_launch(void* const* d_in, const int* in_sizes, int n_in,
                              void* d_out, int out_size)
{
    const float* x     = (const float*)d_in[0];
    const float* b1    = (const float*)d_in[1];
    const float* enc_w = (const float*)d_in[2];
    const float* enc_b = (const float*)d_in[3];
    const float* dec_w = (const float*)d_in[4];
    const float* dec_b = (const float*)d_in[5];

    float* xhat = (float*)d_out;
    float* z    = xhat + (size_t)NROWS * HID;
    __nv_bfloat16* approx = (__nv_bfloat16*)z;   // 536 MB scratch inside z region

    cudaFuncSetAttribute(gemm_hmma, cudaFuncAttributeMaxDynamicSharedMemorySize, GEMM_SMEM);

    // 1) dtype conversions + decoder transpose (fp16)
    conv_x<<<NROWS * HID / 2048, 256>>>(x, b1);
    conv_w<<<(int)((size_t)LAT * HID / 2048), 256>>>(enc_w);
    transpose_dec<<<dim3(LAT / 32, HID / 32), dim3(32, 8)>>>(dec_w);

    // 2) tensor-core encoder GEMM -> bf16 relu scores into z region
    gemm_hmma<<<dim3(LAT / BN, NROWS / BM), 256, GEMM_SMEM>>>(enc_b, approx);

    // 3) per-row top-48 candidates on bf16 scores (histogram, T1=3.0)
    cand_kernel<<<NROWS, 256>>>((const unsigned short*)approx);

    // 4) exact fp32 rescore + exact top-32
    rescore_kernel<<<NROWS, 256>>>(x, b1, enc_w);

    // 5) zero z, scatter
    cudaMemsetAsync(z, 0, (size_t)NROWS * LAT * sizeof(float));
    scatter_kernel<<<(NROWS * TOPK + 255) / 256, 256>>>(z);

    // 6) sparse decode (fp16 weights)
    decode_kernel<<<NROWS, 256>>>(dec_b, xhat);
}

// round 16
// speedup vs baseline: 1.0662x; 1.0662x over previous
#include <cuda_runtime.h>
#include <cuda_bf16.h>
#include <cuda_fp16.h>
#include <cstdint>

#define NROWS 16384
#define HID   2048
#define LAT   16384
#define TOPK  32
#define NCAND 48

// ---------------------------------------------------------------------------
// Device scratch (allocation-free)
// ---------------------------------------------------------------------------
__device__ __nv_bfloat16 g_xb[(size_t)NROWS * HID];   // bf16(x - b1)
__device__ __nv_bfloat16 g_wb[(size_t)LAT * HID];     // bf16(enc_w)
__device__ __half g_dec_h[(size_t)LAT * HID];         // fp16 dec_w transposed
__device__ float g_top_val[(size_t)NROWS * TOPK];
__device__ int   g_top_idx[(size_t)NROWS * TOPK];
__device__ int   g_cand_idx[(size_t)NROWS * NCAND];

// ---------------------------------------------------------------------------
// Helpers
// ---------------------------------------------------------------------------
__device__ __forceinline__ uint32_t smem_u32(const void* p) {
    uint32_t a;
    asm("{ .reg .u64 t; cvta.to.shared.u64 t, %1; cvt.u32.u64 %0, t; }" : "=r"(a) : "l"(p));
    return a;
}
#define CP16(dst, src) \
    asm volatile("cp.async.cg.shared.global [%0], [%1], 16;" :: "r"(dst), "l"(src))
#define CP_COMMIT() asm volatile("cp.async.commit_group;" ::: "memory")
#define CP_WAIT1()  asm volatile("cp.async.wait_group 1;" ::: "memory")

#define LDSM4(r0, r1, r2, r3, addr) \
    asm volatile("ldmatrix.sync.aligned.m8n8.x4.shared.b16 {%0,%1,%2,%3}, [%4];" \
                 : "=r"(r0), "=r"(r1), "=r"(r2), "=r"(r3) : "r"(addr))
#define MMA16816(c, a, b) \
    asm volatile("mma.sync.aligned.m16n8k16.row.col.f32.bf16.bf16.f32 " \
                 "{%0,%1,%2,%3}, {%4,%5,%6,%7}, {%8,%9}, {%0,%1,%2,%3};" \
                 : "+f"((c)[0]), "+f"((c)[1]), "+f"((c)[2]), "+f"((c)[3]) \
                 : "r"((a)[0]), "r"((a)[1]), "r"((a)[2]), "r"((a)[3]), \
                   "r"((b)[0]), "r"((b)[1]))

// ---------------------------------------------------------------------------
// HMMA GEMM (R12/R13 proven): 128x128x64 tiles, 3-stage cp.async, 8 warps,
// 2 CTAs/SM, LDSM4 for both A and B (ni-pairs), multistage prefetch order.
// smem row stride 144B: (144*r) mod 128 = 16*r -> conflict-free ldmatrix.
// ---------------------------------------------------------------------------
#define BM 128
#define BN 128
#define BK 64
#define ROWB 144
#define STG_BYTES (2 * BM * ROWB)        // A + B per stage = 36864 B
#define GEMM_SMEM (3 * STG_BYTES)        // 110592 B
#define NIT (HID / BK)                   // 32

__device__ __forceinline__ void load_stage_g(uint32_t sb, int s, int k0,
                                             int rowBase, int colBase, int tid)
{
    const uint32_t a0 = sb + s * STG_BYTES;
    const uint32_t b0 = a0 + BM * ROWB;
    const __nv_bfloat16* ag = g_xb + (size_t)rowBase * HID + k0;
    const __nv_bfloat16* bg = g_wb + (size_t)colBase * HID + k0;
#pragma unroll
    for (int i = 0; i < 4; ++i) {               // A: 1024 x 16B lines
        int c = tid + i * 256;
        int r = c >> 3, seg = c & 7;
        CP16(a0 + r * ROWB + seg * 16, ag + (size_t)r * HID + seg * 8);
    }
#pragma unroll
    for (int i = 0; i < 4; ++i) {               // B: 1024 x 16B lines
        int c = tid + i * 256;
        int r = c >> 3, seg = c & 7;
        CP16(b0 + r * ROWB + seg * 16, bg + (size_t)r * HID + seg * 8);
    }
}

#define LOAD_FRAGS_AT(slot, ab, bb, ks)                                       \
    do {                                                                      \
        _Pragma("unroll")                                                     \
        for (int mi = 0; mi < 4; ++mi)                                        \
            LDSM4(af[slot][mi][0], af[slot][mi][1],                           \
                  af[slot][mi][2], af[slot][mi][3],                           \
                  (ab) + (uint32_t)(mi * 16) * ROWB + (ks) * 32);             \
        _Pragma("unroll")                                                     \
        for (int ni = 0; ni < 4; ni += 2)                                     \
            LDSM4(bf[slot][ni][0], bf[slot][ni][1],                           \
                  bf[slot][ni + 1][0], bf[slot][ni + 1][1],                   \
                  (bb) + (uint32_t)(ni * 8) * ROWB + (ks) * 32);              \
    } while (0)

__global__ void __launch_bounds__(256, 2)
gemm_hmma(const float* __restrict__ encb, __nv_bfloat16* __restrict__ approx)
{
    extern __shared__ char smem[];
    const uint32_t sb = smem_u32(smem);
    const int tid = threadIdx.x, wid = tid >> 5, lane = tid & 31;
    const int wm = wid >> 2, wn = wid & 3;      // 2x4 warp grid
    const int rowBase = blockIdx.y * BM;
    const int colBase = blockIdx.x * BN;

    float acc[4][4][4];
#pragma unroll
    for (int mi = 0; mi < 4; ++mi)
#pragma unroll
        for (int ni = 0; ni < 4; ++ni)
#pragma unroll
            for (int q = 0; q < 4; ++q) acc[mi][ni][q] = 0.f;

    load_stage_g(sb, 0, 0 * BK, rowBase, colBase, tid); CP_COMMIT();
    load_stage_g(sb, 1, 1 * BK, rowBase, colBase, tid); CP_COMMIT();

    const uint32_t a_row_off = (uint32_t)(wm * 64 + (lane & 15)) * ROWB + (lane >> 4) * 16;
    const uint32_t b_row_off =
        (uint32_t)(wn * 32 + ((lane >> 4) & 1) * 8 + (lane & 7)) * ROWB +
        ((lane >> 3) & 1) * 16;

    uint32_t af[2][4][4], bf[2][4][2];

    CP_WAIT1();
    __syncthreads();
    LOAD_FRAGS_AT(0, sb + a_row_off, sb + BM * ROWB + b_row_off, 0);

    int buf = 0;
    for (int it = 0; it < NIT; ++it) {
        if (it + 2 < NIT)
            load_stage_g(sb, (it + 2) % 3, (it + 2) * BK, rowBase, colBase, tid);
        CP_COMMIT();

        const uint32_t ab  = sb + buf * STG_BYTES + a_row_off;
        const uint32_t bb  = sb + buf * STG_BYTES + BM * ROWB + b_row_off;
        const int nbuf = (buf == 2) ? 0 : buf + 1;
        const uint32_t abn = sb + nbuf * STG_BYTES + a_row_off;
        const uint32_t bbn = sb + nbuf * STG_BYTES + BM * ROWB + b_row_off;

#pragma unroll
        for (int ks = 0; ks < 4; ++ks) {
            const int cur = ks & 1, nx = cur ^ 1;
            if (ks < 3) {
                LOAD_FRAGS_AT(nx, ab, bb, ks + 1);
            } else {
                CP_WAIT1();
                __syncthreads();
                if (it + 1 < NIT)
                    LOAD_FRAGS_AT(nx, abn, bbn, 0);
            }
#pragma unroll
            for (int mi = 0; mi < 4; ++mi)
#pragma unroll
                for (int ni = 0; ni < 4; ++ni)
                    MMA16816(acc[mi][ni], af[cur][mi], bf[cur][ni]);
        }
        buf = nbuf;
    }

    // Epilogue: + enc_b, relu, direct bf16 store
    const int g  = lane >> 2;
    const int tg = lane & 3;
    float2 bias[4];
#pragma unroll
    for (int ni = 0; ni < 4; ++ni)
        bias[ni] = *(const float2*)(encb + colBase + wn * 32 + ni * 8 + tg * 2);

#pragma unroll
    for (int mi = 0; mi < 4; ++mi) {
        const size_t r0 = (size_t)(rowBase + wm * 64 + mi * 16 + g);
        const size_t r1 = r0 + 8;
#pragma unroll
        for (int ni = 0; ni < 4; ++ni) {
            const int col = colBase + wn * 32 + ni * 8 + tg * 2;
            float v00 = fmaxf(acc[mi][ni][0] + bias[ni].x, 0.f);
            float v01 = fmaxf(acc[mi][ni][1] + bias[ni].y, 0.f);
            float v10 = fmaxf(acc[mi][ni][2] + bias[ni].x, 0.f);
            float v11 = fmaxf(acc[mi][ni][3] + bias[ni].y, 0.f);
            __nv_bfloat162 p0 = __floats2bfloat162_rn(v00, v01);
            __nv_bfloat162 p1 = __floats2bfloat162_rn(v10, v11);
            *(__nv_bfloat162*)(approx + r0 * LAT + col) = p0;
            *(__nv_bfloat162*)(approx + r1 * LAT + col) = p1;
        }
    }
}

// ---------------------------------------------------------------------------
// Converters
// ---------------------------------------------------------------------------
__global__ void __launch_bounds__(256) conv_x(const float* __restrict__ x,
                                              const float* __restrict__ b1)
{
    size_t i = ((size_t)blockIdx.x * 256 + threadIdx.x) * 8;
    int col = (int)(i & (HID - 1));
    float4 a0 = *(const float4*)(x + i);
    float4 a1 = *(const float4*)(x + i + 4);
    float4 c0 = *(const float4*)(b1 + col);
    float4 c1 = *(const float4*)(b1 + col + 4);
    __nv_bfloat162 p0 = __floats2bfloat162_rn(a0.x - c0.x, a0.y - c0.y);
    __nv_bfloat162 p1 = __floats2bfloat162_rn(a0.z - c0.z, a0.w - c0.w);
    __nv_bfloat162 p2 = __floats2bfloat162_rn(a1.x - c1.x, a1.y - c1.y);
    __nv_bfloat162 p3 = __floats2bfloat162_rn(a1.z - c1.z, a1.w - c1.w);
    *(uint4*)(g_xb + i) = make_uint4(*(uint32_t*)&p0, *(uint32_t*)&p1,
                                     *(uint32_t*)&p2, *(uint32_t*)&p3);
}

__global__ void __launch_bounds__(256) conv_w(const float* __restrict__ w)
{
    size_t i = ((size_t)blockIdx.x * 256 + threadIdx.x) * 8;
    float4 a0 = *(const float4*)(w + i);
    float4 a1 = *(const float4*)(w + i + 4);
    __nv_bfloat162 p0 = __floats2bfloat162_rn(a0.x, a0.y);
    __nv_bfloat162 p1 = __floats2bfloat162_rn(a0.z, a0.w);
    __nv_bfloat162 p2 = __floats2bfloat162_rn(a1.x, a1.y);
    __nv_bfloat162 p3 = __floats2bfloat162_rn(a1.z, a1.w);
    *(uint4*)(g_wb + i) = make_uint4(*(uint32_t*)&p0, *(uint32_t*)&p1,
                                     *(uint32_t*)&p2, *(uint32_t*)&p3);
}

// ---------------------------------------------------------------------------
// Transpose dec_w [HID, LAT] -> g_dec_h [LAT, HID] (fp16)
// ---------------------------------------------------------------------------
__global__ void __launch_bounds__(256) transpose_dec(const float* __restrict__ dw)
{
    __shared__ float t[32][33];
    const int j0 = blockIdx.x * 32;
    const int h0 = blockIdx.y * 32;
    const int tx = threadIdx.x, ty = threadIdx.y;
#pragma unroll
    for (int dy = 0; dy < 32; dy += 8)
        t[ty + dy][tx] = dw[(size_t)(h0 + ty + dy) * LAT + j0 + tx];
    __syncthreads();
#pragma unroll
    for (int dy = 0; dy < 32; dy += 8)
        g_dec_h[(size_t)(j0 + ty + dy) * HID + h0 + tx] = __float2half(t[tx][ty + dy]);
}

// ---------------------------------------------------------------------------
// Candidate top-48 per row on bf16 approx scores (u16 order == value order).
// R13 exact version: uint4 loads; 2-pass histogram with pass-1 threshold 2.0
// (bf16 0x4000); exact-binary-search fallback when <NCAND values exceed 2.0.
// rv[m] (m = 4*j + w) holds bf16 pair at element index 8*(tid + j*256) + 2*w.
// ---------------------------------------------------------------------------
#define CAND_I0(m) (8 * (tid + ((m) >> 2) * 256) + 2 * ((m) & 3))

__global__ void __launch_bounds__(256) cand_kernel(const unsigned short* __restrict__ approx)
{
    __shared__ unsigned hist[256];
    __shared__ unsigned s_cnt, s_hi, s_g, s_t;
    __shared__ int s_m, s_e;
    __shared__ int gt_idx[NCAND];
    __shared__ int eq_idx[96];

    const int row = blockIdx.x;
    const int tid = threadIdx.x;
    const uint4* src4 = (const uint4*)(approx + (size_t)row * LAT);

    unsigned rv[32];
#pragma unroll
    for (int j = 0; j < 8; ++j) {
        uint4 q = src4[tid + j * 256];
        rv[4 * j + 0] = q.x; rv[4 * j + 1] = q.y;
        rv[4 * j + 2] = q.z; rv[4 * j + 3] = q.w;
    }

    // pass 1: count values > 0x4000 (2.0) and histogram their hi byte (64 bins)
    hist[tid] = 0;
    if (tid == 0) s_cnt = 0;
    __syncthreads();
    unsigned cnt = 0;
#pragma unroll
    for (int m = 0; m < 32; ++m) {
        unsigned v = rv[m];
        unsigned l16 = v & 0xFFFFu, h16 = v >> 16;
        if (l16 > 0x4000u) { atomicAdd(&hist[(l16 >> 8) - 0x40], 1u); ++cnt; }
        if (h16 > 0x4000u) { atomicAdd(&hist[(h16 >> 8) - 0x40], 1u); ++cnt; }
    }
    cnt = __reduce_add_sync(0xFFFFFFFFu, cnt);
    if ((tid & 31) == 0) atomicAdd(&s_cnt, cnt);
    __syncthreads();
    const unsigned total = s_cnt;

    unsigned T;
    if (total >= NCAND) {
        if (tid == 0) {
            unsigned cum = 0;
            for (int b = 63; b >= 0; --b) {
                if (cum + hist[b] >= NCAND) { s_hi = (unsigned)b; s_g = cum; break; }
                cum += hist[b];
            }
        }
        __syncthreads();
        const unsigned hstar = s_hi + 0x40;
        const unsigned G = s_g;
        hist[tid] = 0;
        __syncthreads();
#pragma unroll
        for (int m = 0; m < 32; ++m) {
            unsigned v = rv[m];
            unsigned l16 = v & 0xFFFFu, h16 = v >> 16;
            if ((l16 >> 8) == hstar) atomicAdd(&hist[l16 & 0xFF], 1u);
            if ((h16 >> 8) == hstar) atomicAdd(&hist[h16 & 0xFF], 1u);
        }
        __syncthreads();
        if (tid == 0) {
            unsigned cum = G;
            for (int b = 255; b >= 0; --b) {
                cum += hist[b];
                if (cum >= NCAND) { s_t = (hstar << 8) | (unsigned)b; break; }
            }
        }
        __syncthreads();
        T = s_t;
    } else {
        unsigned lo = 0u, hi = 0x4001u;
        while (lo < hi) {
            unsigned mid = (lo + hi) >> 1;
            if (tid == 0) s_cnt = 0;
            __syncthreads();
            unsigned c = 0;
#pragma unroll
            for (int m = 0; m < 32; ++m) {
                unsigned v = rv[m];
                c += ((v & 0xFFFFu) > mid);
                c += ((v >> 16) > mid);
            }
            c = __reduce_add_sync(0xFFFFFFFFu, c);
            if ((tid & 31) == 0) atomicAdd(&s_cnt, c);
            __syncthreads();
            unsigned tc = s_cnt;
            __syncthreads();
            if (tc >= NCAND) lo = mid + 1; else hi = mid;
        }
        T = lo;
    }

    if (tid == 0) { s_m = 0; s_e = 0; }
    __syncthreads();
#pragma unroll
    for (int m = 0; m < 32; ++m) {
        unsigned v = rv[m];
        int i0 = CAND_I0(m);
        unsigned l16 = v & 0xFFFFu, h16 = v >> 16;
        if (l16 > T)       { int p = atomicAdd(&s_m, 1); if (p < NCAND) gt_idx[p] = i0; }
        else if (l16 == T) { int p = atomicAdd(&s_e, 1); if (p < 96)    eq_idx[p] = i0; }
        if (h16 > T)       { int p = atomicAdd(&s_m, 1); if (p < NCAND) gt_idx[p] = i0 + 1; }
        else if (h16 == T) { int p = atomicAdd(&s_e, 1); if (p < 96)    eq_idx[p] = i0 + 1; }
    }
    __syncthreads();
    if (tid < NCAND) {
        int m = s_m;
        int v = (tid < m) ? gt_idx[tid] : eq_idx[tid - m];
        g_cand_idx[(size_t)row * NCAND + tid] = v;
    }
}

// ---------------------------------------------------------------------------
// Exact fp32 rescore of 48 candidates + exact top-32 (jax tie-break: low idx)
// ---------------------------------------------------------------------------
__global__ void __launch_bounds__(256) rescore_kernel(const float* __restrict__ x,
                                                      const float* __restrict__ b1,
                                                      const float* __restrict__ w)
{
    __shared__ float xs[HID];
    __shared__ float vals[NCAND];
    __shared__ int   cidx[NCAND];
    const int row = blockIdx.x, tid = threadIdx.x;
    const int wid = tid >> 5, lid = tid & 31;

    const float4* xr = (const float4*)(x + (size_t)row * HID);
    const float4* br = (const float4*)b1;
#pragma unroll
    for (int i = 0; i < 2; ++i) {
        int idx = tid + i * 256;
        float4 a = xr[idx], b = br[idx];
        ((float4*)xs)[idx] = make_float4(a.x - b.x, a.y - b.y, a.z - b.z, a.w - b.w);
    }
    if (tid < NCAND) cidx[tid] = g_cand_idx[(size_t)row * NCAND + tid];
    __syncthreads();

    for (int c = wid; c < NCAND; c += 8) {
        const float4* wr = (const float4*)(w + (size_t)cidx[c] * HID);
        float acc = 0.f;
#pragma unroll
        for (int j = 0; j < 16; ++j) {
            float4 wv = wr[lid + j * 32];
            float4 xv = ((const float4*)xs)[lid + j * 32];
            acc = fmaf(wv.x, xv.x, acc);
            acc = fmaf(wv.y, xv.y, acc);
            acc = fmaf(wv.z, xv.z, acc);
            acc = fmaf(wv.w, xv.w, acc);
        }
#pragma unroll
        for (int o = 16; o; o >>= 1) acc += __shfl_xor_sync(0xFFFFFFFFu, acc, o);
        if (lid == 0) vals[c] = fmaxf(acc, 0.f);
    }
    __syncthreads();

    // warp 0: 32 rounds of argmax over 48 (val desc, idx asc)
    if (wid == 0) {
        float v0 = vals[lid];
        int   i0 = cidx[lid];
        float v1 = (lid < NCAND - 32) ? vals[lid + 32] : -2.f;
        int   i1 = (lid < NCAND - 32) ? cidx[lid + 32] : 0x7FFFFFFF;
        size_t base = (size_t)row * TOPK;
        for (int p = 0; p < TOPK; ++p) {
            float mv; int mi;
            if (v0 > v1 || (v0 == v1 && i0 <= i1)) { mv = v0; mi = i0; }
            else                                    { mv = v1; mi = i1; }
            float bv = mv; int bi = mi;
#pragma unroll
            for (int o = 16; o; o >>= 1) {
                float ov = __shfl_xor_sync(0xFFFFFFFFu, bv, o);
                int   oi = __shfl_xor_sync(0xFFFFFFFFu, bi, o);
                if (ov > bv || (ov == bv && oi < bi)) { bv = ov; bi = oi; }
            }
            if (lid == 0) { g_top_val[base + p] = bv; g_top_idx[base + p] = bi; }
            if (i0 == bi) v0 = -1.f;
            if (i1 == bi) v1 = -1.f;
        }
    }
}

// ---------------------------------------------------------------------------
// Sparse decode (fp16 decoder weights, fp32 accumulate) + fused z scatter.
// Launched after cudaMemsetAsync(z): lanes 0-31 write the 32 sparse values.
// ---------------------------------------------------------------------------
__global__ void __launch_bounds__(256) decode_kernel(const float* __restrict__ decb,
                                                     float* __restrict__ xhat,
                                                     float* __restrict__ z)
{
    const int row = blockIdx.x;
    const int tid = threadIdx.x;
    const int c0  = tid * 8;                 // 8 columns per thread
    const size_t base = (size_t)row * TOPK;

    if (tid < TOPK)
        z[(size_t)row * LAT + g_top_idx[base + tid]] = g_top_val[base + tid];

    float a[8];
    float4 b0 = ((const float4*)decb)[tid * 2];
    float4 b1 = ((const float4*)decb)[tid * 2 + 1];
    a[0] = b0.x; a[1] = b0.y; a[2] = b0.z; a[3] = b0.w;
    a[4] = b1.x; a[5] = b1.y; a[6] = b1.z; a[7] = b1.w;

#pragma unroll 4
    for (int k = 0; k < TOPK; ++k) {
        const int   idx = g_top_idx[base + k];
        const float v   = g_top_val[base + k];
        uint4 dv = *(const uint4*)(g_dec_h + (size_t)idx * HID + c0);
        float2 f0 = __half22float2(*(__half2*)&dv.x);
        float2 f1 = __half22float2(*(__half2*)&dv.y);
        float2 f2 = __half22float2(*(__half2*)&dv.z);
        float2 f3 = __half22float2(*(__half2*)&dv.w);
        a[0] = fmaf(v, f0.x, a[0]); a[1] = fmaf(v, f0.y, a[1]);
        a[2] = fmaf(v, f1.x, a[2]); a[3] = fmaf(v, f1.y, a[3]);
        a[4] = fmaf(v, f2.x, a[4]); a[5] = fmaf(v, f2.y, a[5]);
        a[6] = fmaf(v, f3.x, a[6]); a[7] = fmaf(v, f3.y, a[7]);
    }
    float4* out = (float4*)(xhat + (size_t)row * HID + c0);
    out[0] = make_float4(a[0], a[1], a[2], a[3]);
    out[1] = make_float4(a[4], a[5], a[6], a[7]);
}

// ---------------------------------------------------------------------------
// kernel_launch.  Inputs: x, b1, enc_w, enc_b, dec_w, dec_b, topk
// Output: [x_hat (N*HID) | z (N*LAT)] fp32.  z region doubles as bf16 scratch.
// ---------------------------------------------------------------------------
extern "C" void kernel_launch(void* const* d_in, const int* in_sizes, int n_in,
                              void* d_out, int out_size)
{
    const float* x     = (const float*)d_in[0];
    const float* b1    = (const float*)d_in[1];
    const float* enc_w = (const float*)d_in[2];
    const float* enc_b = (const float*)d_in[3];
    const float* dec_w = (const float*)d_in[4];
    const float* dec_b = (const float*)d_in[5];

    float* xhat = (float*)d_out;
    float* z    = xhat + (size_t)NROWS * HID;
    __nv_bfloat16* approx = (__nv_bfloat16*)z;   // 536 MB scratch inside z region

    cudaFuncSetAttribute(gemm_hmma, cudaFuncAttributeMaxDynamicSharedMemorySize, GEMM_SMEM);

    // 1) dtype conversions + decoder transpose (fp16)
    conv_x<<<NROWS * HID / 2048, 256>>>(x, b1);
    conv_w<<<(int)((size_t)LAT * HID / 2048), 256>>>(enc_w);
    transpose_dec<<<dim3(LAT / 32, HID / 32), dim3(32, 8)>>>(dec_w);

    // 2) tensor-core encoder GEMM -> bf16 relu scores into z region
    gemm_hmma<<<dim3(LAT / BN, NROWS / BM), 256, GEMM_SMEM>>>(enc_b, approx);

    // 3) per-row top-48 candidates on bf16 scores (histogram, T1=2.0)
    cand_kernel<<<NROWS, 256>>>((const unsigned short*)approx);

    // 4) exact fp32 rescore + exact top-32
    rescore_kernel<<<NROWS, 256>>>(x, b1, enc_w);

    // 5) zero z, then decode with fused scatter (writes z sparse + x_hat)
    cudaMemsetAsync(z, 0, (size_t)NROWS * LAT * sizeof(float));
    decode_kernel<<<NROWS, 256>>>(dec_b, xhat, z);
}